// round 8
// baseline (speedup 1.0000x reference)
#include <cuda_runtime.h>
#include <cuda_bf16.h>

// BandedJointEncoder: closed-form inverse of per-(b,z) upper-bidiagonal U.
//   d[t] = mapped[b,t,32+2z] + 1 ; s[t] = mapped[b,t,33+2z]
//   L[r,c] = inv_d[r] * prod_{k=c}^{r-1} (-s_k/d_k)  for r >= c, else 0
// Outputs: mean [B,Z,T] then cov_tril_lower [B,Z,T,T].
//
// R8: per-SM store-path test. Same warp store pattern as the R5 best
// (4 consecutive cols/thread, contiguous 512B STG.128 per warp, __stcs),
// but grid = (B*Z, 2) x 256 threads: 256 CTAs engage all 148 SMs
// (grid=128 left 20 SMs idle). Each CTA owns 256 rows of one (b,z).

#define T_DIM 512
#define Z_DIM 32
#define C_DIM 96

__global__ __launch_bounds__(256)
void banded_joint_encoder_kernel(const float* __restrict__ in,
                                 float* __restrict__ out_mean,
                                 float* __restrict__ out_cov)
{
    const int bz  = blockIdx.x;          // b*Z + z
    const int b   = bz >> 5;
    const int z   = bz & 31;
    const int tid = threadIdx.x;         // 0..255

    __shared__ float2 sh_ti[T_DIM];      // {t[k], inv_d[k]}
    __shared__ float  sh_b8[T_DIM / 8];  // 8-term block products of t

    // ---- prologue: each thread loads 2 rows of t / inv_d ----
    #pragma unroll
    for (int h = 0; h < 2; ++h) {
        const int row = tid + h * 256;
        const float* row_in = in + ((size_t)b * T_DIM + row) * C_DIM;
        float dv  = row_in[32 + 2 * z] + 1.0f;
        float sv  = row_in[33 + 2 * z];
        float inv = 1.0f / dv;
        sh_ti[row] = make_float2(-sv * inv, inv);
        if (blockIdx.y == 0)
            out_mean[(size_t)bz * T_DIM + row] = row_in[z];
    }
    __syncthreads();

    if (tid < T_DIM / 8) {
        int k0 = tid * 8;
        float bprod = sh_ti[k0].x;
        #pragma unroll
        for (int j = 1; j < 8; ++j) bprod *= sh_ti[k0 + j].x;
        sh_b8[tid] = bprod;
    }
    __syncthreads();

    const int g  = tid >> 7;                          // row group 0..1
    const int l  = tid & 127;                         // column quad 0..127
    const int c0 = l << 2;                            // first of 4 owned cols
    const int R0 = (blockIdx.y << 8) + (g << 7);      // first of 128 rows

    // ---- seed running products p_j = prod_{k=c0+j}^{R0-1} t_k ----
    float p3 = 1.f;
    {
        int k = c0 + 3;
        if (k < R0) {
            int e = (k + 7) & ~7;        // R0 % 8 == 0 -> e <= R0
            for (; k < e; ++k)          p3 *= sh_ti[k].x;
            for (; k + 8 <= R0; k += 8) p3 *= sh_b8[k >> 3];
        }
    }
    float p2 = (c0 + 2 < R0) ? sh_ti[c0 + 2].x * p3 : 1.f;
    float p1 = (c0 + 1 < R0) ? sh_ti[c0 + 1].x * p2 : 1.f;
    float p0 = (c0     < R0) ? sh_ti[c0    ].x * p1 : 1.f;

    // ---- main loop: 128 rows, one streaming STG.128 per row per thread ----
    float4* out4 = (float4*)(out_cov + (size_t)bz * T_DIM * T_DIM) + l;

    #pragma unroll 4
    for (int r = R0; r < R0 + 128; ++r) {
        const float2 ti = sh_ti[r];      // broadcast LDS.64, conflict-free
        const float tv = ti.x, iv = ti.y;

        float4 v;
        bool a0 = (r >= c0);
        bool a1 = (r >= c0 + 1);
        bool a2 = (r >= c0 + 2);
        bool a3 = (r >= c0 + 3);
        v.x = a0 ? p0 * iv : 0.f;
        v.y = a1 ? p1 * iv : 0.f;
        v.z = a2 ? p2 * iv : 0.f;
        v.w = a3 ? p3 * iv : 0.f;
        if (a0) p0 *= tv;
        if (a1) p1 *= tv;
        if (a2) p2 *= tv;
        if (a3) p3 *= tv;

        __stcs(&out4[(size_t)r * (T_DIM / 4)], v);   // st.global.cs.v4.f32
    }
}

extern "C" void kernel_launch(void* const* d_in, const int* in_sizes, int n_in,
                              void* d_out, int out_size)
{
    const float* in = (const float*)d_in[0];
    float* out = (float*)d_out;

    const int B = in_sizes[0] / (T_DIM * C_DIM);

    float* out_mean = out;                                // [B, Z, T]
    float* out_cov  = out + (size_t)B * Z_DIM * T_DIM;    // [B, Z, T, T]

    dim3 grid(B * Z_DIM, 2);
    banded_joint_encoder_kernel<<<grid, 256>>>(in, out_mean, out_cov);
}

// round 9
// speedup vs baseline: 1.0822x; 1.0822x over previous
#include <cuda_runtime.h>
#include <cuda_bf16.h>

// BandedJointEncoder: closed-form inverse of per-(b,z) upper-bidiagonal U.
//   d[t] = mapped[b,t,32+2z] + 1 ; s[t] = mapped[b,t,33+2z]
//   L[r,c] = inv_d[r] * prod_{k=c}^{r-1} (-s_k/d_k)  for r >= c, else 0
// Outputs: mean [B,Z,T] then cov_tril_lower [B,Z,T,T].
//
// FINAL: grid = B*Z CTAs x 512 threads (single wave). Thread owns 4
// CONSECUTIVE columns -> each warp's STG.128 covers 512B fully contiguous.
// Streaming hint (__stcs): output is write-once, larger than L2.
// Measured ~98.5% of the chip-global ~3100 B/cyc L2-write ceiling, which
// 7 structural variants (scalar/vector/TMA/multi-wave) all bracket.

#define T_DIM 512
#define Z_DIM 32
#define C_DIM 96

__global__ __launch_bounds__(T_DIM)
void banded_joint_encoder_kernel(const float* __restrict__ in,
                                 float* __restrict__ out_mean,
                                 float* __restrict__ out_cov)
{
    const int bz  = blockIdx.x;          // b*Z + z
    const int b   = bz >> 5;
    const int z   = bz & 31;
    const int tid = threadIdx.x;

    __shared__ float2 sh_ti[T_DIM];      // {t[k], inv_d[k]}
    __shared__ float  sh_b8[T_DIM / 8];  // 8-term block products of t

    // ---- prologue: per-row t / inv_d, mean output ----
    {
        const float* row_in = in + ((size_t)b * T_DIM + tid) * C_DIM;
        float dv  = row_in[32 + 2 * z] + 1.0f;
        float sv  = row_in[33 + 2 * z];
        float inv = 1.0f / dv;
        sh_ti[tid] = make_float2(-sv * inv, inv);
        out_mean[(size_t)bz * T_DIM + tid] = row_in[z];
    }
    __syncthreads();

    if (tid < T_DIM / 8) {
        int k0 = tid * 8;
        float bprod = sh_ti[k0].x;
        #pragma unroll
        for (int j = 1; j < 8; ++j) bprod *= sh_ti[k0 + j].x;
        sh_b8[tid] = bprod;
    }
    __syncthreads();

    const int g  = tid >> 7;             // row group 0..3 (128 rows each)
    const int l  = tid & 127;            // column quad 0..127
    const int c0 = l << 2;               // first of 4 owned columns
    const int R0 = g << 7;               // first row of this group

    // ---- seed running products p_j = prod_{k=c0+j}^{R0-1} t_k ----
    float p3 = 1.f;
    {
        int k = c0 + 3;
        if (k < R0) {
            int e = (k + 7) & ~7;        // R0 % 8 == 0 -> e <= R0
            for (; k < e; ++k)          p3 *= sh_ti[k].x;
            for (; k + 8 <= R0; k += 8) p3 *= sh_b8[k >> 3];
        }
    }
    float p2 = (c0 + 2 < R0) ? sh_ti[c0 + 2].x * p3 : 1.f;
    float p1 = (c0 + 1 < R0) ? sh_ti[c0 + 1].x * p2 : 1.f;
    float p0 = (c0     < R0) ? sh_ti[c0    ].x * p1 : 1.f;

    // ---- main loop: 128 rows, one streaming STG.128 per row per thread ----
    float4* out4 = (float4*)(out_cov + (size_t)bz * T_DIM * T_DIM) + l;

    #pragma unroll 4
    for (int r = R0; r < R0 + 128; ++r) {
        const float2 ti = sh_ti[r];      // broadcast LDS.64, conflict-free
        const float tv = ti.x, iv = ti.y;

        float4 v;
        bool a0 = (r >= c0);
        bool a1 = (r >= c0 + 1);
        bool a2 = (r >= c0 + 2);
        bool a3 = (r >= c0 + 3);
        v.x = a0 ? p0 * iv : 0.f;
        v.y = a1 ? p1 * iv : 0.f;
        v.z = a2 ? p2 * iv : 0.f;
        v.w = a3 ? p3 * iv : 0.f;
        if (a0) p0 *= tv;
        if (a1) p1 *= tv;
        if (a2) p2 *= tv;
        if (a3) p3 *= tv;

        __stcs(&out4[(size_t)r * (T_DIM / 4)], v);   // st.global.cs.v4.f32
    }
}

extern "C" void kernel_launch(void* const* d_in, const int* in_sizes, int n_in,
                              void* d_out, int out_size)
{
    const float* in = (const float*)d_in[0];
    float* out = (float*)d_out;

    const int B = in_sizes[0] / (T_DIM * C_DIM);

    float* out_mean = out;                                // [B, Z, T]
    float* out_cov  = out + (size_t)B * Z_DIM * T_DIM;    // [B, Z, T, T]

    banded_joint_encoder_kernel<<<B * Z_DIM, T_DIM>>>(in, out_mean, out_cov);
}

// round 10
// speedup vs baseline: 1.1102x; 1.0259x over previous
#include <cuda_runtime.h>
#include <cuda_bf16.h>

// BandedJointEncoder: closed-form inverse of per-(b,z) upper-bidiagonal U.
//   d[t] = mapped[b,t,32+2z] + 1 ; s[t] = mapped[b,t,33+2z]
//   L[r,c] = inv_d[r] * prod_{k=c}^{r-1} (-s_k/d_k)  for r >= c, else 0
// Outputs: mean [B,Z,T] then cov_tril_lower [B,Z,T,T].
//
// FINAL: grid = B*Z CTAs x 512 threads (single wave). Thread owns 4
// CONSECUTIVE columns -> each warp's STG.128 covers 512B fully contiguous.
// Streaming hint (__stcs): output is write-once, larger than L2.
// Steady-state replays are DRAM-write bound (134.5 MB mandatory bytes at
// ~5.85 TB/s write-only HBM3e ceiling); 7 structural variants bracket it.
// This config measured fastest and is ~98-99% of that roofline.

#define T_DIM 512
#define Z_DIM 32
#define C_DIM 96

__global__ __launch_bounds__(T_DIM)
void banded_joint_encoder_kernel(const float* __restrict__ in,
                                 float* __restrict__ out_mean,
                                 float* __restrict__ out_cov)
{
    const int bz  = blockIdx.x;          // b*Z + z
    const int b   = bz >> 5;
    const int z   = bz & 31;
    const int tid = threadIdx.x;

    __shared__ float2 sh_ti[T_DIM];      // {t[k], inv_d[k]}
    __shared__ float  sh_b8[T_DIM / 8];  // 8-term block products of t

    // ---- prologue: per-row t / inv_d, mean output ----
    {
        const float* row_in = in + ((size_t)b * T_DIM + tid) * C_DIM;
        float dv  = row_in[32 + 2 * z] + 1.0f;
        float sv  = row_in[33 + 2 * z];
        float inv = 1.0f / dv;
        sh_ti[tid] = make_float2(-sv * inv, inv);
        out_mean[(size_t)bz * T_DIM + tid] = row_in[z];
    }
    __syncthreads();

    if (tid < T_DIM / 8) {
        int k0 = tid * 8;
        float bprod = sh_ti[k0].x;
        #pragma unroll
        for (int j = 1; j < 8; ++j) bprod *= sh_ti[k0 + j].x;
        sh_b8[tid] = bprod;
    }
    __syncthreads();

    const int g  = tid >> 7;             // row group 0..3 (128 rows each)
    const int l  = tid & 127;            // column quad 0..127
    const int c0 = l << 2;               // first of 4 owned columns
    const int R0 = g << 7;               // first row of this group

    // ---- seed running products p_j = prod_{k=c0+j}^{R0-1} t_k ----
    float p3 = 1.f;
    {
        int k = c0 + 3;
        if (k < R0) {
            int e = (k + 7) & ~7;        // R0 % 8 == 0 -> e <= R0
            for (; k < e; ++k)          p3 *= sh_ti[k].x;
            for (; k + 8 <= R0; k += 8) p3 *= sh_b8[k >> 3];
        }
    }
    float p2 = (c0 + 2 < R0) ? sh_ti[c0 + 2].x * p3 : 1.f;
    float p1 = (c0 + 1 < R0) ? sh_ti[c0 + 1].x * p2 : 1.f;
    float p0 = (c0     < R0) ? sh_ti[c0    ].x * p1 : 1.f;

    // ---- main loop: 128 rows, one streaming STG.128 per row per thread ----
    float4* out4 = (float4*)(out_cov + (size_t)bz * T_DIM * T_DIM) + l;

    #pragma unroll 4
    for (int r = R0; r < R0 + 128; ++r) {
        const float2 ti = sh_ti[r];      // broadcast LDS.64, conflict-free
        const float tv = ti.x, iv = ti.y;

        float4 v;
        bool a0 = (r >= c0);
        bool a1 = (r >= c0 + 1);
        bool a2 = (r >= c0 + 2);
        bool a3 = (r >= c0 + 3);
        v.x = a0 ? p0 * iv : 0.f;
        v.y = a1 ? p1 * iv : 0.f;
        v.z = a2 ? p2 * iv : 0.f;
        v.w = a3 ? p3 * iv : 0.f;
        if (a0) p0 *= tv;
        if (a1) p1 *= tv;
        if (a2) p2 *= tv;
        if (a3) p3 *= tv;

        __stcs(&out4[(size_t)r * (T_DIM / 4)], v);   // st.global.cs.v4.f32
    }
}

extern "C" void kernel_launch(void* const* d_in, const int* in_sizes, int n_in,
                              void* d_out, int out_size)
{
    const float* in = (const float*)d_in[0];
    float* out = (float*)d_out;

    const int B = in_sizes[0] / (T_DIM * C_DIM);

    float* out_mean = out;                                // [B, Z, T]
    float* out_cov  = out + (size_t)B * Z_DIM * T_DIM;    // [B, Z, T, T]

    banded_joint_encoder_kernel<<<B * Z_DIM, T_DIM>>>(in, out_mean, out_cov);
}